// round 1
// baseline (speedup 1.0000x reference)
#include <cuda_runtime.h>
#include <cstdint>

// TopK per row: B x D fp32, top-k along D, ReLU, scatter into zeros.
// One CTA per row. Fused: histogram select (12-bit ordered-key bins) +
// output write in two passes; 2nd pass should hit L2 (occupancy capped so
// concurrent rows fit in 126MB L2).

namespace {

constexpr int TPB   = 512;
constexpr int NB    = 4096;     // 12-bit key bins
constexpr int SEG   = NB / TPB; // bins per thread in the scan (8)
constexpr int CAP   = 4096;     // candidate buffer capacity
constexpr int D_DIM = 65536;
constexpr unsigned SMEM_BYTES = 75 * 1024; // padded to cap occupancy at 3 CTAs/SM

__device__ __forceinline__ unsigned orderKey(float f) {
    unsigned u = __float_as_uint(f);
    // monotonic map: float order -> unsigned order
    return u ^ ((u & 0x80000000u) ? 0xFFFFFFFFu : 0x80000000u);
}

__device__ __forceinline__ float keyToFloat(unsigned key) {
    unsigned u = (key & 0x80000000u) ? (key ^ 0x80000000u) : ~key;
    return __uint_as_float(u);
}

__global__ void __launch_bounds__(TPB, 3)
topk_rowselect_kernel(const float* __restrict__ x,
                      const int* __restrict__ kptr,
                      float* __restrict__ out)
{
    extern __shared__ unsigned smem_u[];
    unsigned* hist    = smem_u;            // NB
    unsigned* ckey    = hist + NB;         // CAP
    unsigned* cidx    = ckey + CAP;        // CAP
    unsigned* partial = cidx + CAP;        // TPB
    __shared__ unsigned s_bin, s_rank, s_cnt;

    const int tid = threadIdx.x;
    const int row = blockIdx.x;
    const unsigned k = (unsigned)__ldg(kptr);

    const float4* rowv = reinterpret_cast<const float4*>(x) + (size_t)row * (D_DIM / 4);
    float4*       outv = reinterpret_cast<float4*>(out)     + (size_t)row * (D_DIM / 4);

    for (int i = tid; i < NB; i += TPB) hist[i] = 0u;
    if (tid == 0) s_cnt = 0u;
    __syncthreads();

    // ---- Phase 1: histogram of top-12 key bits (1 GiB HBM read total) ----
    for (int i = tid; i < D_DIM / 4; i += TPB) {
        float4 v = rowv[i];
        atomicAdd(&hist[orderKey(v.x) >> 20], 1u);
        atomicAdd(&hist[orderKey(v.y) >> 20], 1u);
        atomicAdd(&hist[orderKey(v.z) >> 20], 1u);
        atomicAdd(&hist[orderKey(v.w) >> 20], 1u);
    }
    __syncthreads();

    // ---- Find critical bin: suffix scan from the top ----
    {
        unsigned s = 0;
        #pragma unroll
        for (int j = 0; j < SEG; ++j) s += hist[tid * SEG + j];
        partial[tid] = s;
    }
    __syncthreads();
    // inclusive suffix sums over the 512 segment partials
    for (int off = 1; off < TPB; off <<= 1) {
        unsigned v = partial[tid];
        unsigned a = (tid + off < TPB) ? partial[tid + off] : 0u;
        __syncthreads();
        partial[tid] = v + a;
        __syncthreads();
    }
    {
        unsigned St = partial[tid];
        unsigned Sn = (tid + 1 < TPB) ? partial[tid + 1] : 0u;
        if (St >= k && Sn < k) {
            // critical segment is mine; descend its 8 bins from the top
            unsigned acc = Sn;
            #pragma unroll
            for (int j = SEG - 1; j >= 0; --j) {
                unsigned c = hist[tid * SEG + j];
                if (acc + c >= k) { s_bin = (unsigned)(tid * SEG + j); s_rank = k - acc; break; }
                acc += c;
            }
        }
    }
    __syncthreads();
    const unsigned bcrit = s_bin;
    const unsigned rneed = s_rank;

    // ---- Phase 2: write output (streaming), collect critical-bin candidates ----
    for (int i = tid; i < D_DIM / 4; i += TPB) {
        float4 v = __ldcs(&rowv[i]);   // re-read: should be L2-resident
        float vv[4] = {v.x, v.y, v.z, v.w};
        float ov[4];
        #pragma unroll
        for (int l = 0; l < 4; ++l) {
            unsigned key = orderKey(vv[l]);
            unsigned bin = key >> 20;
            if (bin > bcrit) {
                ov[l] = fmaxf(vv[l], 0.0f);     // definitely in top-k
            } else {
                ov[l] = 0.0f;
                if (bin == bcrit) {
                    unsigned p = atomicAdd(&s_cnt, 1u);
                    if (p < CAP) { ckey[p] = key; cidx[p] = (unsigned)(i * 4 + l); }
                }
            }
        }
        float4 o = make_float4(ov[0], ov[1], ov[2], ov[3]);
        __stcs(&outv[i], o);
    }
    __syncthreads();

    // ---- Phase 3: exact rank among candidates (tiny; O(cnt^2)) ----
    const unsigned cnt = min(s_cnt, (unsigned)CAP);
    for (unsigned j = tid; j < cnt; j += TPB) {
        const unsigned kj = ckey[j], ij = cidx[j];
        unsigned rank = 0;
        for (unsigned t = 0; t < cnt; ++t) {
            const unsigned kt = ckey[t];
            rank += (kt > kj) || (kt == kj && cidx[t] < ij);
        }
        if (rank < rneed) {
            out[(size_t)row * D_DIM + ij] = fmaxf(keyToFloat(kj), 0.0f);
        }
    }
}

} // namespace

extern "C" void kernel_launch(void* const* d_in, const int* in_sizes, int n_in,
                              void* d_out, int out_size)
{
    const float* x  = (const float*)d_in[0];
    const int*   kp = (const int*)d_in[1];
    float*       out = (float*)d_out;

    const int rows = in_sizes[0] / D_DIM;

    cudaFuncSetAttribute(topk_rowselect_kernel,
                         cudaFuncAttributeMaxDynamicSharedMemorySize, SMEM_BYTES);
    topk_rowselect_kernel<<<rows, TPB, SMEM_BYTES>>>(x, kp, out);
}